// round 15
// baseline (speedup 1.0000x reference)
#include <cuda_runtime.h>
#include <cstdint>

// Problem constants (fixed by setup_inputs)
#define B_    32
#define C_    128
#define H_    32
#define W_    32
#define PHh   16
#define PWw   16
#define NPOS  (C_*PHh*PWw)     // 32768
#define POSB  16               // positions per tile
#define NTILES 2               // tiles per block (software pipeline depth)
#define NTHREADS 256
#define NBLK  (NPOS/(POSB*NTILES))   // 1024

#define LOG2E 1.4426950408889634f
#define LN2   0.6931471805599453f

// Dynamic smem layout (bytes)
#define RAW_OFF   0                    // 4 tensors x 32 b x 256B (2 rows)  = 32768
#define RAWE_OFF  32768                // eps: 32 b x 64B                   = 2048
#define SAB_OFF   34816                // ulonglong2 [32][16]               = 8192
#define SG_OFF    43008                // ull        [32][16]               = 4096
#define ZST_OFF   47104                // float      [16][33] (padded)      = 2112
#define SMEM_TOTAL 49216

typedef unsigned long long ull;

__device__ float g_partial[NBLK];
__device__ unsigned int g_count = 0;   // returns to 0 at the end of every call

static __device__ __forceinline__ float ex2f_(float x){ float y; asm("ex2.approx.ftz.f32 %0, %1;":"=f"(y):"f"(x)); return y; }
static __device__ __forceinline__ float lg2f_(float x){ float y; asm("lg2.approx.ftz.f32 %0, %1;":"=f"(y):"f"(x)); return y; }
static __device__ __forceinline__ float rcpf_(float x){ float y; asm("rcp.approx.ftz.f32 %0, %1;":"=f"(y):"f"(x)); return y; }
static __device__ __forceinline__ float sqrtaf_(float x){ float y; asm("sqrt.approx.ftz.f32 %0, %1;":"=f"(y):"f"(x)); return y; }

// Blackwell packed f32x2 FMA (PTX-only). Each half is IEEE fma.rn -> bit-identical to scalar.
static __device__ __forceinline__ ull fma2_(ull a, ull b, ull c){
    ull d; asm("fma.rn.f32x2 %0, %1, %2, %3;":"=l"(d):"l"(a),"l"(b),"l"(c)); return d;
}
static __device__ __forceinline__ ull pack2_(float lo, float hi){
    ull r; asm("mov.b64 %0, {%1, %2};":"=l"(r):"f"(lo),"f"(hi)); return r;
}
static __device__ __forceinline__ void unpack2_(ull v, float& lo, float& hi){
    asm("mov.b64 {%0, %1}, %2;":"=f"(lo),"=f"(hi):"l"(v));
}

static __device__ __forceinline__ void cpa16_(uint32_t s, const void* g){
    asm volatile("cp.async.cg.shared.global [%0], [%1], 16;"::"r"(s),"l"(g):"memory");
}

// Prefetch one tile's raw inputs into shared (2176 x 16B cp.async ops over 256 threads).
static __device__ __forceinline__ void prefetch_tile(
    uint32_t sbase,
    const float* __restrict__ mua, const float* __restrict__ lva,
    const float* __restrict__ mub, const float* __restrict__ lvb,
    const float* __restrict__ eps, int tile, int tid)
{
    int g0 = tile * POSB;
    int c  = g0 >> 8;
    int ph = (g0 >> 4) & 15;
    #pragma unroll
    for (int r = 0; r < 9; ++r) {
        int o = tid + r * NTHREADS;
        if (o < 2048) {
            int T   = o >> 9;          // tensor
            int rem = o & 511;
            int b   = rem >> 4;        // batch row
            int u   = rem & 15;        // 16B unit within the 2-row (256B) chunk
            const float* src = (T == 0) ? mua : (T == 1) ? lva : (T == 2) ? mub : lvb;
            const float* g = src + (size_t)((b * C_ + c) * H_ + 2 * ph) * W_ + u * 4;
            cpa16_(sbase + RAW_OFF + (o << 4), g);   // o*16 == (T*8192 + b*256 + u*16)
        } else if (o < 2176) {
            int e = o - 2048;
            int b = e >> 2;
            int u = e & 3;
            const float* g = eps + (size_t)((b * C_ + c) * PHh + ph) * PWw + u * 4;
            cpa16_(sbase + RAWE_OFF + (e << 4), g);  // e*16 == (b*64 + u*16)
        }
    }
    asm volatile("cp.async.commit_group;" ::: "memory");
}

__global__ void __launch_bounds__(NTHREADS, 4) kl_main(
    const float* __restrict__ mua, const float* __restrict__ lva,
    const float* __restrict__ mub, const float* __restrict__ lvb,
    const float* __restrict__ eps, float* __restrict__ out)
{
    extern __shared__ char smem[];
    const uint32_t sbase = (uint32_t)__cvta_generic_to_shared(smem);

    // Coefficient views (R10/R14-proven layout)
    ulonglong2 (*sab)[POSB] = (ulonglong2(*)[POSB])(smem + SAB_OFF);
    ull        (*sg )[POSB] = (ull       (*)[POSB])(smem + SG_OFF);
    float      (*zst)[33]   = (float     (*)[33]  )(smem + ZST_OFF);  // [p][b], padded

    __shared__ float red[8];
    __shared__ int   is_last;

    const int tid  = threadIdx.x;
    const int lane = tid & 31;
    const int wid  = tid >> 5;
    const int blk  = blockIdx.x;

    // Kick off the DMA for tile 0 immediately.
    prefetch_tile(sbase, mua, lva, mub, lvb, eps, blk * NTILES, tid);

    float acc = 0.0f;

    #pragma unroll 1
    for (int t = 0; t < NTILES; ++t) {
        asm volatile("cp.async.wait_group 0;" ::: "memory");
        __syncthreads();   // raw[t] visible to all; also: phase2(t-1) coeff readers done

        // ---- Convert: raw smem -> coefficients (identical math to R14 phase 1) ----
        {
            int b  = tid >> 3;
            int wp = tid & 7;
            int p0 = 2 * wp;

            const float4* r_mua = (const float4*)(smem + RAW_OFF);            // [b*16 + u]
            const float4* r_lva = (const float4*)(smem + RAW_OFF + 8192);
            const float4* r_mub = (const float4*)(smem + RAW_OFF + 16384);
            const float4* r_lvb = (const float4*)(smem + RAW_OFF + 24576);
            const float2* r_eps = (const float2*)(smem + RAWE_OFF);           // [b*8 + wp]

            float4 a0  = r_mua[b * 16 + wp];
            float4 a1  = r_mua[b * 16 + 8 + wp];
            float4 la0 = r_lva[b * 16 + wp];
            float4 la1 = r_lva[b * 16 + 8 + wp];
            float4 b0  = r_mub[b * 16 + wp];
            float4 b1  = r_mub[b * 16 + 8 + wp];
            float4 lb0 = r_lvb[b * 16 + wp];
            float4 lb1 = r_lvb[b * 16 + 8 + wp];
            float2 e   = r_eps[b * 8 + wp];

            float ma0 = (a0.x + a0.y + a1.x + a1.y) * 0.25f;
            float ma1 = (a0.z + a0.w + a1.z + a1.w) * 0.25f;
            float mb0 = (b0.x + b0.y + b1.x + b1.y) * 0.25f;
            float mb1 = (b0.z + b0.w + b1.z + b1.w) * 0.25f;
            float va0 = (ex2f_(la0.x * LOG2E) + ex2f_(la0.y * LOG2E) +
                         ex2f_(la1.x * LOG2E) + ex2f_(la1.y * LOG2E)) * 0.0625f;
            float va1 = (ex2f_(la0.z * LOG2E) + ex2f_(la0.w * LOG2E) +
                         ex2f_(la1.z * LOG2E) + ex2f_(la1.w * LOG2E)) * 0.0625f;
            float vb0 = (ex2f_(lb0.x * LOG2E) + ex2f_(lb0.y * LOG2E) +
                         ex2f_(lb1.x * LOG2E) + ex2f_(lb1.y * LOG2E)) * 0.0625f;
            float vb1 = (ex2f_(lb0.z * LOG2E) + ex2f_(lb0.w * LOG2E) +
                         ex2f_(lb1.z * LOG2E) + ex2f_(lb1.w * LOG2E)) * 0.0625f;

            float aa0 = (-0.5f * LOG2E) * rcpf_(va0);
            float aa1 = (-0.5f * LOG2E) * rcpf_(va1);
            float ab0 = (-0.5f * LOG2E) * rcpf_(vb0);
            float ab1 = (-0.5f * LOG2E) * rcpf_(vb1);

            float ba0 = -2.0f * aa0 * ma0, bb0 = -2.0f * ab0 * mb0;
            float ba1 = -2.0f * aa1 * ma1, bb1 = -2.0f * ab1 * mb1;
            float ga0 = fmaf(aa0 * ma0, ma0, -0.5f * lg2f_(va0));
            float gb0 = fmaf(ab0 * mb0, mb0, -0.5f * lg2f_(vb0));
            float ga1 = fmaf(aa1 * ma1, ma1, -0.5f * lg2f_(va1));
            float gb1 = fmaf(ab1 * mb1, mb1, -0.5f * lg2f_(vb1));

            sab[b][p0]     = make_ulonglong2(pack2_(aa0, ab0), pack2_(ba0, bb0));
            sab[b][p0 + 1] = make_ulonglong2(pack2_(aa1, ab1), pack2_(ba1, bb1));
            sg [b][p0]     = pack2_(ga0, gb0);
            sg [b][p0 + 1] = pack2_(ga1, gb1);
            zst[p0][b]     = fmaf(sqrtaf_(va0), e.x, ma0);
            zst[p0 + 1][b] = fmaf(sqrtaf_(va1), e.y, ma1);
        }
        __syncthreads();   // coeffs ready; all raw reads done

        // Overlap: start the DMA for the next tile while phase 2 runs.
        if (t + 1 < NTILES)
            prefetch_tile(sbase, mua, lva, mub, lvb, eps, blk * NTILES + t + 1, tid);

        // ---- Phase 2: pairwise densities (byte-for-byte R10/R14 inner loop) ----
        #pragma unroll 1
        for (int pp = 0; pp < 2; ++pp) {
            int p = wid * 2 + pp;
            float zi = zst[p][lane];
            ull   zp = pack2_(zi, zi);

            float Sa0 = 0.0f, Sb0 = 0.0f, Sa1 = 0.0f, Sb1 = 0.0f;
            #pragma unroll
            for (int j = 0; j < B_; j += 2) {
                ulonglong2 q0 = sab[j][p];       // broadcast LDS.128
                ull        g0 = sg [j][p];       // broadcast LDS.64
                ulonglong2 q1 = sab[j + 1][p];
                ull        g1 = sg [j + 1][p];
                ull arg0 = fma2_(fma2_(q0.x, zp, q0.y), zp, g0);
                ull arg1 = fma2_(fma2_(q1.x, zp, q1.y), zp, g1);
                float xa0, xb0, xa1, xb1;
                unpack2_(arg0, xa0, xb0);
                unpack2_(arg1, xa1, xb1);
                Sa0 += ex2f_(xa0);
                Sb0 += ex2f_(xb0);
                Sa1 += ex2f_(xa1);
                Sb1 += ex2f_(xb1);
            }

            float Sa = Sa0 + Sa1, Sb = Sb0 + Sb1;
            // term = ln(Sa/32 + 1e-6) - ln(Sb/32 + 1e-6) = ln2 * (lg2(.) - lg2(.))
            acc += lg2f_(fmaf(Sa, 0.03125f, 1e-6f)) - lg2f_(fmaf(Sb, 0.03125f, 1e-6f));
        }
        __syncthreads();   // phase2 done before next convert overwrites coeffs
    }
    acc *= LN2;

    // ---- Reduce: warp -> block -> global partial ----
    #pragma unroll
    for (int o = 16; o; o >>= 1) acc += __shfl_xor_sync(0xffffffffu, acc, o);
    if (lane == 0) red[wid] = acc;
    __syncthreads();
    if (tid == 0) {
        float v = 0.0f;
        #pragma unroll
        for (int i = 0; i < 8; ++i) v += red[i];
        g_partial[blk] = v;
        __threadfence();
        unsigned int tcount = atomicAdd(&g_count, 1u);
        is_last = (tcount == NBLK - 1) ? 1 : 0;
    }
    __syncthreads();

    // ---- Last block performs the final (order-deterministic) reduction ----
    if (is_last) {
        float s = 0.0f;
        #pragma unroll
        for (int i = tid; i < NBLK; i += NTHREADS) s += g_partial[i];
        #pragma unroll
        for (int o = 16; o; o >>= 1) s += __shfl_xor_sync(0xffffffffu, s, o);
        if (lane == 0) red[wid] = s;
        __syncthreads();
        if (tid == 0) {
            float v = 0.0f;
            #pragma unroll
            for (int i = 0; i < 8; ++i) v += red[i];
            out[0] = 32.0f * v;      // torch loop multiplies the grand sum by B
            g_count = 0;             // reset for next (graph-replayed) call
        }
    }
}

extern "C" void kernel_launch(void* const* d_in, const int* in_sizes, int n_in,
                              void* d_out, int out_size)
{
    (void)in_sizes; (void)n_in; (void)out_size;
    const float* mua = (const float*)d_in[0];
    const float* lva = (const float*)d_in[1];
    const float* mub = (const float*)d_in[2];
    const float* lvb = (const float*)d_in[3];
    const float* eps = (const float*)d_in[4];
    // d_in[5] = kern (int32 scalar), fixed to 2 for this problem.

    static int attr_set = 0;
    if (!attr_set) {
        cudaFuncSetAttribute(kl_main, cudaFuncAttributeMaxDynamicSharedMemorySize, SMEM_TOTAL);
        attr_set = 1;
    }
    kl_main<<<NBLK, NTHREADS, SMEM_TOTAL>>>(mua, lva, mub, lvb, eps, (float*)d_out);
}

// round 16
// speedup vs baseline: 1.1633x; 1.1633x over previous
#include <cuda_runtime.h>

// Problem constants (fixed by setup_inputs)
#define B_    32
#define C_    128
#define H_    32
#define W_    32
#define PHh   16
#define PWw   16
#define NPOS  (C_*PHh*PWw)     // 32768
#define POSB  16               // positions per block
#define NTHREADS 256
#define NBLK  (NPOS/POSB)      // 2048

#define LOG2E 1.4426950408889634f
#define LN2   0.6931471805599453f

typedef unsigned long long ull;

__device__ float g_partial[NBLK];
__device__ unsigned int g_count = 0;   // returns to 0 at the end of every call

static __device__ __forceinline__ float ex2f_(float x){ float y; asm("ex2.approx.ftz.f32 %0, %1;":"=f"(y):"f"(x)); return y; }
static __device__ __forceinline__ float lg2f_(float x){ float y; asm("lg2.approx.ftz.f32 %0, %1;":"=f"(y):"f"(x)); return y; }
static __device__ __forceinline__ float rcpf_(float x){ float y; asm("rcp.approx.ftz.f32 %0, %1;":"=f"(y):"f"(x)); return y; }
static __device__ __forceinline__ float sqrtaf_(float x){ float y; asm("sqrt.approx.ftz.f32 %0, %1;":"=f"(y):"f"(x)); return y; }

// Blackwell packed f32x2 FMA (PTX-only). Each half is IEEE fma.rn -> bit-identical to scalar.
static __device__ __forceinline__ ull fma2_(ull a, ull b, ull c){
    ull d; asm("fma.rn.f32x2 %0, %1, %2, %3;":"=l"(d):"l"(a),"l"(b),"l"(c)); return d;
}
static __device__ __forceinline__ ull pack2_(float lo, float hi){
    ull r; asm("mov.b64 %0, {%1, %2};":"=l"(r):"f"(lo),"f"(hi)); return r;
}
static __device__ __forceinline__ void unpack2_(ull v, float& lo, float& hi){
    asm("mov.b64 {%0, %1}, %2;":"=f"(lo),"=f"(hi):"l"(v));
}

__global__ void __launch_bounds__(NTHREADS, 4) kl_main(
    const float* __restrict__ mua, const float* __restrict__ lva,
    const float* __restrict__ mub, const float* __restrict__ lvb,
    const float* __restrict__ eps, float* __restrict__ out)
{
    // Packed polynomial coefficients per (row j, position p) -- R10/R14-proven layout:
    //   arg_m = (alpha_m*z + beta_m)*z + gamma_m for m in {a,b}, both halves in one f32x2 pair
    __shared__ ulonglong2 sab[B_][POSB];     // { (aa,ab), (ba,bb) } 16B -> LDS.128
    __shared__ ull        sg [B_][POSB];     // { (ga,gb) }           8B -> LDS.64
    __shared__ float      zs [B_][POSB + 1]; // +1 pad: conflict-free lane-i reads
    __shared__ float      red[8];
    __shared__ int        is_last;

    const int tid   = threadIdx.x;
    const int gbase = blockIdx.x * POSB;

    // ---- Phase 1: pooling + coefficient build, ONE round (task == thread) ----
    {
        int b   = tid >> 3;
        int wp  = tid & 7;
        int p0  = 2 * wp;
        int g   = gbase + p0;
        int c   = g >> 8;
        int ph  = (g >> 4) & 15;
        int pw0 = g & 15;

        int base = ((b * C_ + c) * H_ + 2 * ph) * W_ + 2 * pw0;

        float4 a0  = *(const float4*)(mua + base);
        float4 a1  = *(const float4*)(mua + base + W_);
        float4 la0 = *(const float4*)(lva + base);
        float4 la1 = *(const float4*)(lva + base + W_);
        float4 b0  = *(const float4*)(mub + base);
        float4 b1  = *(const float4*)(mub + base + W_);
        float4 lb0 = *(const float4*)(lvb + base);
        float4 lb1 = *(const float4*)(lvb + base + W_);
        float2 e   = *(const float2*)(eps + ((b * C_ + c) * PHh + ph) * PWw + pw0);

        // window 0 = .x/.y, window 1 = .z/.w
        float ma0 = (a0.x + a0.y + a1.x + a1.y) * 0.25f;
        float ma1 = (a0.z + a0.w + a1.z + a1.w) * 0.25f;
        float mb0 = (b0.x + b0.y + b1.x + b1.y) * 0.25f;
        float mb1 = (b0.z + b0.w + b1.z + b1.w) * 0.25f;
        // var = avgpool(exp(logvar)) / 4 = sum(exp)/16
        float va0 = (ex2f_(la0.x * LOG2E) + ex2f_(la0.y * LOG2E) +
                     ex2f_(la1.x * LOG2E) + ex2f_(la1.y * LOG2E)) * 0.0625f;
        float va1 = (ex2f_(la0.z * LOG2E) + ex2f_(la0.w * LOG2E) +
                     ex2f_(la1.z * LOG2E) + ex2f_(la1.w * LOG2E)) * 0.0625f;
        float vb0 = (ex2f_(lb0.x * LOG2E) + ex2f_(lb0.y * LOG2E) +
                     ex2f_(lb1.x * LOG2E) + ex2f_(lb1.y * LOG2E)) * 0.0625f;
        float vb1 = (ex2f_(lb0.z * LOG2E) + ex2f_(lb0.w * LOG2E) +
                     ex2f_(lb1.z * LOG2E) + ex2f_(lb1.w * LOG2E)) * 0.0625f;

        // alpha = -log2e/(2v); beta = -2*alpha*mu; gamma = alpha*mu^2 - 0.5*lg2(v)
        float aa0 = (-0.5f * LOG2E) * rcpf_(va0);
        float aa1 = (-0.5f * LOG2E) * rcpf_(va1);
        float ab0 = (-0.5f * LOG2E) * rcpf_(vb0);
        float ab1 = (-0.5f * LOG2E) * rcpf_(vb1);

        float ba0 = -2.0f * aa0 * ma0, bb0 = -2.0f * ab0 * mb0;
        float ba1 = -2.0f * aa1 * ma1, bb1 = -2.0f * ab1 * mb1;
        float ga0 = fmaf(aa0 * ma0, ma0, -0.5f * lg2f_(va0));
        float gb0 = fmaf(ab0 * mb0, mb0, -0.5f * lg2f_(vb0));
        float ga1 = fmaf(aa1 * ma1, ma1, -0.5f * lg2f_(va1));
        float gb1 = fmaf(ab1 * mb1, mb1, -0.5f * lg2f_(vb1));

        sab[b][p0]     = make_ulonglong2(pack2_(aa0, ab0), pack2_(ba0, bb0));
        sab[b][p0 + 1] = make_ulonglong2(pack2_(aa1, ab1), pack2_(ba1, bb1));
        sg [b][p0]     = pack2_(ga0, gb0);
        sg [b][p0 + 1] = pack2_(ga1, gb1);
        zs [b][p0]     = fmaf(sqrtaf_(va0), e.x, ma0);
        zs [b][p0 + 1] = fmaf(sqrtaf_(va1), e.y, ma1);
    }
    __syncthreads();

    // ---- Phase 2: warp w handles BOTH its positions (2w, 2w+1) in ONE fused j-loop.
    // 4 independent ex2 chains (one (Sa,Sb) pair per position); lane = i.
    // End-of-loop lg2 tails for p0/p1 are independent -> tail latency halves vs R14.
    const int lane = tid & 31;
    const int wid  = tid >> 5;
    const int p0   = wid * 2;
    const int p1   = p0 + 1;

    float zi0 = zs[lane][p0];
    float zi1 = zs[lane][p1];
    ull   zp0 = pack2_(zi0, zi0);
    ull   zp1 = pack2_(zi1, zi1);

    float Sa0 = 0.0f, Sb0 = 0.0f, Sa1 = 0.0f, Sb1 = 0.0f;
    #pragma unroll
    for (int j = 0; j < B_; ++j) {
        ulonglong2 q0 = sab[j][p0];      // broadcast LDS.128
        ull        g0 = sg [j][p0];      // broadcast LDS.64
        ulonglong2 q1 = sab[j][p1];
        ull        g1 = sg [j][p1];
        ull arg0 = fma2_(fma2_(q0.x, zp0, q0.y), zp0, g0);
        ull arg1 = fma2_(fma2_(q1.x, zp1, q1.y), zp1, g1);
        float xa0, xb0, xa1, xb1;
        unpack2_(arg0, xa0, xb0);
        unpack2_(arg1, xa1, xb1);
        Sa0 += ex2f_(xa0);
        Sb0 += ex2f_(xb0);
        Sa1 += ex2f_(xa1);
        Sb1 += ex2f_(xb1);
    }

    // term = ln(S/32 + 1e-6) diff; the two position tails are independent MUFU chains
    float t0 = lg2f_(fmaf(Sa0, 0.03125f, 1e-6f)) - lg2f_(fmaf(Sb0, 0.03125f, 1e-6f));
    float t1 = lg2f_(fmaf(Sa1, 0.03125f, 1e-6f)) - lg2f_(fmaf(Sb1, 0.03125f, 1e-6f));
    float acc = (t0 + t1) * LN2;

    // ---- Reduce: warp -> block -> global partial ----
    #pragma unroll
    for (int o = 16; o; o >>= 1) acc += __shfl_xor_sync(0xffffffffu, acc, o);
    if (lane == 0) red[wid] = acc;
    __syncthreads();
    if (tid == 0) {
        float v = 0.0f;
        #pragma unroll
        for (int i = 0; i < 8; ++i) v += red[i];
        g_partial[blockIdx.x] = v;
        __threadfence();
        unsigned int t = atomicAdd(&g_count, 1u);
        is_last = (t == NBLK - 1) ? 1 : 0;
    }
    __syncthreads();

    // ---- Last block performs the final (order-deterministic) reduction ----
    if (is_last) {
        float s = 0.0f;
        #pragma unroll
        for (int i = tid; i < NBLK; i += NTHREADS) s += g_partial[i];
        #pragma unroll
        for (int o = 16; o; o >>= 1) s += __shfl_xor_sync(0xffffffffu, s, o);
        if (lane == 0) red[wid] = s;
        __syncthreads();
        if (tid == 0) {
            float v = 0.0f;
            #pragma unroll
            for (int i = 0; i < 8; ++i) v += red[i];
            out[0] = 32.0f * v;      // torch loop multiplies the grand sum by B
            g_count = 0;             // reset for next (graph-replayed) call
        }
    }
}

extern "C" void kernel_launch(void* const* d_in, const int* in_sizes, int n_in,
                              void* d_out, int out_size)
{
    (void)in_sizes; (void)n_in; (void)out_size;
    const float* mua = (const float*)d_in[0];
    const float* lva = (const float*)d_in[1];
    const float* mub = (const float*)d_in[2];
    const float* lvb = (const float*)d_in[3];
    const float* eps = (const float*)d_in[4];
    // d_in[5] = kern (int32 scalar), fixed to 2 for this problem.

    kl_main<<<NBLK, NTHREADS>>>(mua, lva, mub, lvb, eps, (float*)d_out);
}

// round 17
// speedup vs baseline: 1.2632x; 1.0859x over previous
#include <cuda_runtime.h>

// Problem constants (fixed by setup_inputs)
#define B_    32
#define C_    128
#define H_    32
#define W_    32
#define PHh   16
#define PWw   16
#define NPOS  (C_*PHh*PWw)     // 32768
#define POSB  16               // positions per tile
#define NTILE (NPOS/POSB)      // 2048 tiles
#define NTHREADS 256
#define NBLK  592              // persistent: 148 SMs x 4 resident blocks

#define LOG2E 1.4426950408889634f
#define LN2   0.6931471805599453f

typedef unsigned long long ull;

__device__ float g_partial[NBLK];
__device__ unsigned int g_count = 0;   // returns to 0 at the end of every call

static __device__ __forceinline__ float ex2f_(float x){ float y; asm("ex2.approx.ftz.f32 %0, %1;":"=f"(y):"f"(x)); return y; }
static __device__ __forceinline__ float lg2f_(float x){ float y; asm("lg2.approx.ftz.f32 %0, %1;":"=f"(y):"f"(x)); return y; }
static __device__ __forceinline__ float rcpf_(float x){ float y; asm("rcp.approx.ftz.f32 %0, %1;":"=f"(y):"f"(x)); return y; }
static __device__ __forceinline__ float sqrtaf_(float x){ float y; asm("sqrt.approx.ftz.f32 %0, %1;":"=f"(y):"f"(x)); return y; }

// Blackwell packed f32x2 FMA (PTX-only). Each half is IEEE fma.rn -> bit-identical to scalar.
static __device__ __forceinline__ ull fma2_(ull a, ull b, ull c){
    ull d; asm("fma.rn.f32x2 %0, %1, %2, %3;":"=l"(d):"l"(a),"l"(b),"l"(c)); return d;
}
static __device__ __forceinline__ ull pack2_(float lo, float hi){
    ull r; asm("mov.b64 %0, {%1, %2};":"=l"(r):"f"(lo),"f"(hi)); return r;
}
static __device__ __forceinline__ void unpack2_(ull v, float& lo, float& hi){
    asm("mov.b64 {%0, %1}, %2;":"=f"(lo),"=f"(hi):"l"(v));
}

__global__ void __launch_bounds__(NTHREADS, 4) kl_main(
    const float* __restrict__ mua, const float* __restrict__ lva,
    const float* __restrict__ mub, const float* __restrict__ lvb,
    const float* __restrict__ eps, float* __restrict__ out)
{
    // Packed polynomial coefficients per (row j, position p) -- R10/R14-proven layout:
    //   arg_m = (alpha_m*z + beta_m)*z + gamma_m for m in {a,b}, both halves in one f32x2 pair
    __shared__ ulonglong2 sab[B_][POSB];     // { (aa,ab), (ba,bb) } 16B -> LDS.128
    __shared__ ull        sg [B_][POSB];     // { (ga,gb) }           8B -> LDS.64
    __shared__ float      zs [B_][POSB + 1]; // +1 pad: conflict-free lane-i reads
    __shared__ float      red[8];
    __shared__ int        is_last;

    const int tid  = threadIdx.x;
    const int lane = tid & 31;
    const int wid  = tid >> 5;
    const int blk  = blockIdx.x;

    float acc = 0.0f;

    // ---- Persistent tile loop: block handles tiles blk, blk+592, ... ----
    #pragma unroll 1
    for (int tile = blk; tile < NTILE; tile += NBLK) {
        const int gbase = tile * POSB;

        // ---- Phase 1: pooling + coefficient build, ONE round (task == thread) ----
        {
            int b   = tid >> 3;
            int wp  = tid & 7;
            int p0  = 2 * wp;
            int g   = gbase + p0;
            int c   = g >> 8;
            int ph  = (g >> 4) & 15;
            int pw0 = g & 15;

            int base = ((b * C_ + c) * H_ + 2 * ph) * W_ + 2 * pw0;

            float4 a0  = *(const float4*)(mua + base);
            float4 a1  = *(const float4*)(mua + base + W_);
            float4 la0 = *(const float4*)(lva + base);
            float4 la1 = *(const float4*)(lva + base + W_);
            float4 b0  = *(const float4*)(mub + base);
            float4 b1  = *(const float4*)(mub + base + W_);
            float4 lb0 = *(const float4*)(lvb + base);
            float4 lb1 = *(const float4*)(lvb + base + W_);
            float2 e   = *(const float2*)(eps + ((b * C_ + c) * PHh + ph) * PWw + pw0);

            // window 0 = .x/.y, window 1 = .z/.w
            float ma0 = (a0.x + a0.y + a1.x + a1.y) * 0.25f;
            float ma1 = (a0.z + a0.w + a1.z + a1.w) * 0.25f;
            float mb0 = (b0.x + b0.y + b1.x + b1.y) * 0.25f;
            float mb1 = (b0.z + b0.w + b1.z + b1.w) * 0.25f;
            // var = avgpool(exp(logvar)) / 4 = sum(exp)/16
            float va0 = (ex2f_(la0.x * LOG2E) + ex2f_(la0.y * LOG2E) +
                         ex2f_(la1.x * LOG2E) + ex2f_(la1.y * LOG2E)) * 0.0625f;
            float va1 = (ex2f_(la0.z * LOG2E) + ex2f_(la0.w * LOG2E) +
                         ex2f_(la1.z * LOG2E) + ex2f_(la1.w * LOG2E)) * 0.0625f;
            float vb0 = (ex2f_(lb0.x * LOG2E) + ex2f_(lb0.y * LOG2E) +
                         ex2f_(lb1.x * LOG2E) + ex2f_(lb1.y * LOG2E)) * 0.0625f;
            float vb1 = (ex2f_(lb0.z * LOG2E) + ex2f_(lb0.w * LOG2E) +
                         ex2f_(lb1.z * LOG2E) + ex2f_(lb1.w * LOG2E)) * 0.0625f;

            // alpha = -log2e/(2v); beta = -2*alpha*mu; gamma = alpha*mu^2 - 0.5*lg2(v)
            float aa0 = (-0.5f * LOG2E) * rcpf_(va0);
            float aa1 = (-0.5f * LOG2E) * rcpf_(va1);
            float ab0 = (-0.5f * LOG2E) * rcpf_(vb0);
            float ab1 = (-0.5f * LOG2E) * rcpf_(vb1);

            float ba0 = -2.0f * aa0 * ma0, bb0 = -2.0f * ab0 * mb0;
            float ba1 = -2.0f * aa1 * ma1, bb1 = -2.0f * ab1 * mb1;
            float ga0 = fmaf(aa0 * ma0, ma0, -0.5f * lg2f_(va0));
            float gb0 = fmaf(ab0 * mb0, mb0, -0.5f * lg2f_(vb0));
            float ga1 = fmaf(aa1 * ma1, ma1, -0.5f * lg2f_(va1));
            float gb1 = fmaf(ab1 * mb1, mb1, -0.5f * lg2f_(vb1));

            sab[b][p0]     = make_ulonglong2(pack2_(aa0, ab0), pack2_(ba0, bb0));
            sab[b][p0 + 1] = make_ulonglong2(pack2_(aa1, ab1), pack2_(ba1, bb1));
            sg [b][p0]     = pack2_(ga0, gb0);
            sg [b][p0 + 1] = pack2_(ga1, gb1);
            zs [b][p0]     = fmaf(sqrtaf_(va0), e.x, ma0);
            zs [b][p0 + 1] = fmaf(sqrtaf_(va1), e.y, ma1);
        }
        __syncthreads();

        // ---- Phase 2: warp w handles positions [2w, 2w+2), lane = i (R14 byte-for-byte) ----
        #pragma unroll 1
        for (int pp = 0; pp < 2; ++pp) {
            int p = wid * 2 + pp;
            float zi = zs[lane][p];
            ull   zp = pack2_(zi, zi);

            // 2-way j unroll -> 4 independent scalar ex2+FADD chains
            float Sa0 = 0.0f, Sb0 = 0.0f, Sa1 = 0.0f, Sb1 = 0.0f;
            #pragma unroll
            for (int j = 0; j < B_; j += 2) {
                ulonglong2 q0 = sab[j][p];       // broadcast LDS.128
                ull        g0 = sg [j][p];       // broadcast LDS.64
                ulonglong2 q1 = sab[j + 1][p];
                ull        g1 = sg [j + 1][p];
                ull arg0 = fma2_(fma2_(q0.x, zp, q0.y), zp, g0);
                ull arg1 = fma2_(fma2_(q1.x, zp, q1.y), zp, g1);
                float xa0, xb0, xa1, xb1;
                unpack2_(arg0, xa0, xb0);
                unpack2_(arg1, xa1, xb1);
                Sa0 += ex2f_(xa0);
                Sb0 += ex2f_(xb0);
                Sa1 += ex2f_(xa1);
                Sb1 += ex2f_(xb1);
            }

            float Sa = Sa0 + Sa1, Sb = Sb0 + Sb1;
            // term = ln(Sa/32 + 1e-6) - ln(Sb/32 + 1e-6) = ln2 * (lg2(.) - lg2(.))
            acc += lg2f_(fmaf(Sa, 0.03125f, 1e-6f)) - lg2f_(fmaf(Sb, 0.03125f, 1e-6f));
        }
        __syncthreads();   // phase-2 reads drain before next tile's phase-1 overwrites smem
    }
    acc *= LN2;

    // ---- Reduce: warp -> block -> global partial ----
    #pragma unroll
    for (int o = 16; o; o >>= 1) acc += __shfl_xor_sync(0xffffffffu, acc, o);
    if (lane == 0) red[wid] = acc;
    __syncthreads();
    if (tid == 0) {
        float v = 0.0f;
        #pragma unroll
        for (int i = 0; i < 8; ++i) v += red[i];
        g_partial[blk] = v;
        __threadfence();
        unsigned int t = atomicAdd(&g_count, 1u);
        is_last = (t == NBLK - 1) ? 1 : 0;
    }
    __syncthreads();

    // ---- Last block performs the final (order-deterministic) reduction ----
    if (is_last) {
        float s = 0.0f;
        #pragma unroll
        for (int i = tid; i < NBLK; i += NTHREADS) s += g_partial[i];
        #pragma unroll
        for (int o = 16; o; o >>= 1) s += __shfl_xor_sync(0xffffffffu, s, o);
        if (lane == 0) red[wid] = s;
        __syncthreads();
        if (tid == 0) {
            float v = 0.0f;
            #pragma unroll
            for (int i = 0; i < 8; ++i) v += red[i];
            out[0] = 32.0f * v;      // torch loop multiplies the grand sum by B
            g_count = 0;             // reset for next (graph-replayed) call
        }
    }
}

extern "C" void kernel_launch(void* const* d_in, const int* in_sizes, int n_in,
                              void* d_out, int out_size)
{
    (void)in_sizes; (void)n_in; (void)out_size;
    const float* mua = (const float*)d_in[0];
    const float* lva = (const float*)d_in[1];
    const float* mub = (const float*)d_in[2];
    const float* lvb = (const float*)d_in[3];
    const float* eps = (const float*)d_in[4];
    // d_in[5] = kern (int32 scalar), fixed to 2 for this problem.

    kl_main<<<NBLK, NTHREADS>>>(mua, lva, mub, lvb, eps, (float*)d_out);
}